// round 17
// baseline (speedup 1.0000x reference)
#include <cuda_runtime.h>
#include <cuda_bf16.h>
#include <cstdint>

#define TDIM 512
#define NREC 256
#define NIN 10
#define NOUT 3
#define BATCH 1024
#define ROWS 8
#define NB (BATCH/ROWS)     // 128 blocks
#define NT 512              // 16 warps; warp w owns m-tile w (m in [16w,16w+16))

// SMEM byte offsets
#define WHI_OFF  0          // Whi bf16 [256 m][256 k], 512B rows, XOR-swizzled
#define RB0H_OFF 131072     // r bf16 hi/lo, 2 buffers, [8 n][528B]
#define RB0L_OFF 135296
#define RB1H_OFF 139520
#define RB1L_OFF 143744
#define UD_OFF   147968     // u drive fp32 [8 n][260 words] (bias + xWin + noise)
#define WOS_OFF  156288     // W_out [3][256]
#define XB_OFF   159360     // x staging [2][8][12] = 768 B
#define ZP_OFF   160128     // z partials [16 w][26 floats]
#define SMEM_BYTES 161792

__device__ uint4 g_wlo[16*16*32];   // Wlo bf16 in A-fragment order, 128 KB
__device__ float g_l2p[NB];
__device__ unsigned int g_ctr;

static __device__ __forceinline__ uint32_t smem_u32(const void* p){
    uint32_t a; asm("{ .reg .u64 t; cvta.to.shared.u64 t, %1; cvt.u32.u64 %0, t; }":"=r"(a):"l"(p)); return a;
}
static __device__ __forceinline__ uint16_t bfu(float f){
    __nv_bfloat16 h = __float2bfloat16(f); return *(uint16_t*)&h;
}
static __device__ __forceinline__ float bff(uint16_t u){
    __nv_bfloat16 h = *(__nv_bfloat16*)&u; return __bfloat162float(h);
}
static __device__ __forceinline__ void ldsm4(uint32_t* r, uint32_t addr){
    asm volatile("ldmatrix.sync.aligned.m8n8.x4.shared.b16 {%0,%1,%2,%3}, [%4];"
        : "=r"(r[0]),"=r"(r[1]),"=r"(r[2]),"=r"(r[3]) : "r"(addr));
}
static __device__ __forceinline__ void mma16816(float* d, const uint32_t* a, const uint32_t* b){
    asm volatile("mma.sync.aligned.m16n8k16.row.col.f32.bf16.bf16.f32 "
        "{%0,%1,%2,%3}, {%4,%5,%6,%7}, {%8,%9}, {%0,%1,%2,%3};"
        : "+f"(d[0]),"+f"(d[1]),"+f"(d[2]),"+f"(d[3])
        : "r"(a[0]),"r"(a[1]),"r"(a[2]),"r"(a[3]), "r"(b[0]),"r"(b[1]));
}
static __device__ __forceinline__ uint32_t lds32(uint32_t addr){
    uint32_t v; asm volatile("ld.shared.b32 %0, [%1];" : "=r"(v) : "r"(addr)); return v;
}

// one-time: Wlo (bf16 residual) in exact m16n8k16 A-fragment order
__global__ void prep_kernel(const float* __restrict__ W){
    int idx = blockIdx.x * 256 + threadIdx.x;     // 0..8191
    int t = idx >> 5, l = idx & 31;
    int mt = t >> 4, kt = t & 15;
    int g = l >> 2, c = l & 3;
    int m0 = mt * 16 + g, k0 = kt * 16 + c * 2;
    uint32_t r[4];
    #pragma unroll
    for (int q = 0; q < 4; q++){
        int m = m0 + ((q & 1) ? 8 : 0);
        int k = k0 + ((q & 2) ? 8 : 0);
        float w0 = W[m * NREC + k],  w1 = W[m * NREC + k + 1];
        uint16_t l0 = bfu(w0 - bff(bfu(w0)));
        uint16_t l1 = bfu(w1 - bff(bfu(w1)));
        r[q] = (uint32_t)l0 | ((uint32_t)l1 << 16);
    }
    g_wlo[idx] = make_uint4(r[0], r[1], r[2], r[3]);
}

__global__ __launch_bounds__(NT, 1)
void rnn_kernel(const float* __restrict__ x,
                const float* __restrict__ noise,
                const float* __restrict__ W_in,
                const float* __restrict__ W_rec,
                const float* __restrict__ W_out,
                const float* __restrict__ b_out,
                const float* __restrict__ bias,
                float* __restrict__ out, int out_size)
{
    extern __shared__ char sm[];
    const uint32_t sb = smem_u32(sm);
    float* udS = (float*)(sm + UD_OFF);
    float* WoS = (float*)(sm + WOS_OFF);
    float* xb  = (float*)(sm + XB_OFF);
    float* zpS = (float*)(sm + ZP_OFF);

    const int tid = threadIdx.x;
    const int w = tid >> 5, l = tid & 31;
    const int g = l >> 2, c = l & 3;
    const int b0 = blockIdx.x * ROWS;
    const int cm = tid & 255;          // udS column owner
    const int n0 = (tid >> 8) * 4;     // udS row group (0..3 or 4..7)

    // ---- init Whi in SMEM (bf16, swizzled) ----
    for (int i = tid; i < NREC * NREC; i += NT){
        int m = i >> 8, k = i & 255;
        uint16_t h = bfu(W_rec[m * NREC + k]);
        int k16 = k >> 3;
        uint32_t off = (uint32_t)m * 512 + (uint32_t)((k16 ^ (m & 7)) << 4) + (uint32_t)((k & 7) * 2);
        *(uint16_t*)(sm + WHI_OFF + off) = h;
    }
    for (int i = tid; i < (4 * 4224) / 4; i += NT)
        *(uint32_t*)(sm + RB0H_OFF + i * 4) = 0;
    for (int i = tid; i < NOUT * NREC; i += NT) WoS[i] = W_out[i];
    if (tid < ROWS * NIN){
        int i = tid / NIN, k = tid % NIN;
        xb[i * 12 + k] = x[(size_t)(b0 + i) * TDIM * NIN + k];
    }

    float win[NIN];
    #pragma unroll
    for (int k = 0; k < NIN; k++) win[k] = W_in[cm * NIN + k];
    const float bsm = bias[cm];
    const float bo0 = b_out[0], bo1 = b_out[1], bo2 = b_out[2];

    float rold[4];
    #pragma unroll
    for (int s = 0; s < 4; s++) rold[s] = 0.f;
    double l2d = 0.0;

    // coalesced noise prefetch for my 4 rows (one step ahead)
    float nzr[4];
    #pragma unroll
    for (int i = 0; i < 4; i++)
        nzr[i] = noise[((size_t)(b0 + n0 + i) * TDIM + 0) * NREC + cm];

    // ldmatrix lane addressing
    const int rowL = l & 15, hiL = l >> 4, xrL = l & 7;
    const uint32_t aBase = sb + WHI_OFF + (uint32_t)((16 * w + rowL) * 512);

    __syncthreads();

    const uint32_t rbH[2] = { sb + RB0H_OFF, sb + RB1H_OFF };
    const uint32_t rbL[2] = { sb + RB0L_OFF, sb + RB1L_OFF };

    for (int ts = 0; ts < TDIM; ts++){
        const int cur = ts & 1, nxt = cur ^ 1;
        const float* xbc = xb + cur * 96;
        float*       xbn = xb + nxt * 96;

        // ---- phase 1: u drive for my 4 rows (coalesced), next-x stage ----
        #pragma unroll
        for (int i = 0; i < 4; i++){
            float u = bsm + nzr[i];
            #pragma unroll
            for (int k = 0; k < NIN; k++) u = fmaf(xbc[(n0 + i) * 12 + k], win[k], u);
            udS[(n0 + i) * 260 + cm] = u;
        }
        if (tid < ROWS * NIN){
            int i = tid / NIN, k = tid % NIN;
            int tn = (ts + 1 < TDIM) ? ts + 1 : ts;
            xbn[i * 12 + k] = x[((size_t)(b0 + i) * TDIM + tn) * NIN + k];
        }
        __syncthreads();   // barrier 1: ud visible; prev rbf writes visible

        // next-step noise prefetch (hidden under MMA)
        {
            int tn = (ts + 1 < TDIM) ? ts + 1 : ts;
            #pragma unroll
            for (int i = 0; i < 4; i++)
                nzr[i] = noise[((size_t)(b0 + n0 + i) * TDIM + tn) * NREC + cm];
        }

        // ---- phase 2: MMA over 16 k-tiles, 3 independent chains ----
        float dA[4], dB[4], dC[4];
        #pragma unroll
        for (int j = 0; j < 4; j++){ dA[j] = 0.f; dB[j] = 0.f; dC[j] = 0.f; }

        const uint32_t bHbase = rbH[cur] + (uint32_t)((l >> 2) * 528 + (l & 3) * 4);
        const uint32_t bLbase = rbL[cur] + (uint32_t)((l >> 2) * 528 + (l & 3) * 4);

        // Wlo stream pipeline, distance 4
        uint4 wbuf[4];
        #pragma unroll
        for (int p = 0; p < 4; p++)
            wbuf[p] = g_wlo[(w * 16 + p) * 32 + l];

        uint32_t bh[2][2], bl[2][2], ah[2][4];
        bh[0][0] = lds32(bHbase);
        bh[0][1] = lds32(bHbase + 16);
        bl[0][0] = lds32(bLbase);
        bl[0][1] = lds32(bLbase + 16);
        ldsm4(ah[0], aBase + (uint32_t)(((0 + hiL) ^ xrL) << 4));

        #pragma unroll
        for (int kt = 0; kt < 16; kt++){
            const int cb = kt & 1, nb = cb ^ 1;
            if (kt < 15){
                uint32_t bo = bHbase + (uint32_t)((kt + 1) * 32);
                bh[nb][0] = lds32(bo);
                bh[nb][1] = lds32(bo + 16);
                uint32_t bo2 = bLbase + (uint32_t)((kt + 1) * 32);
                bl[nb][0] = lds32(bo2);
                bl[nb][1] = lds32(bo2 + 16);
                ldsm4(ah[nb], aBase + (uint32_t)(((2 * (kt + 1) + hiL) ^ xrL) << 4));
            }
            mma16816(dA, ah[cb], bh[cb]);                          // Whi*rhi
            mma16816(dB, ah[cb], bl[cb]);                          // Whi*rlo
            mma16816(dC, (const uint32_t*)&wbuf[kt & 3], bh[cb]);  // Wlo*rhi
            if (kt + 4 < 16)
                wbuf[kt & 3] = g_wlo[(w * 16 + kt + 4) * 32 + l];
        }

        // ---- combine: r update, publish bf16 hi/lo, z partials in regs ----
        const int mA = 16 * w + g;        // m for j=0,1
        const int mB = mA + 8;            // m for j=2,3
        float woA0 = WoS[mA], woA1 = WoS[256 + mA], woA2 = WoS[512 + mA];
        float woB0 = WoS[mB], woB1 = WoS[256 + mB], woB2 = WoS[512 + mB];
        float zp0[3] = {0.f, 0.f, 0.f};   // n = 2c
        float zp1[3] = {0.f, 0.f, 0.f};   // n = 2c+1
        float ssum = 0.f;
        #pragma unroll
        for (int j = 0; j < 4; j++){
            const int mS = (j & 2) ? mB : mA;
            const int nS = (c << 1) + (j & 1);
            float v = dA[j] + dB[j] + dC[j] + udS[nS * 260 + mS];
            float rn = 0.8f * rold[j] + 0.2f * fmaxf(v, 0.f);
            rold[j] = rn;
            uint16_t h  = bfu(rn);
            uint16_t lo = bfu(rn - bff(h));
            uint32_t ro = (uint32_t)(nS * 528 + mS * 2);
            *(uint16_t*)(sm + (rbH[nxt] - sb) + ro) = h;
            *(uint16_t*)(sm + (rbL[nxt] - sb) + ro) = lo;
            ssum = fmaf(rn, rn, ssum);
            float w0 = (j & 2) ? woB0 : woA0;
            float w1 = (j & 2) ? woB1 : woA1;
            float w2 = (j & 2) ? woB2 : woA2;
            if (j & 1){
                zp1[0] = fmaf(rn, w0, zp1[0]);
                zp1[1] = fmaf(rn, w1, zp1[1]);
                zp1[2] = fmaf(rn, w2, zp1[2]);
            } else {
                zp0[0] = fmaf(rn, w0, zp0[0]);
                zp0[1] = fmaf(rn, w1, zp0[1]);
                zp0[2] = fmaf(rn, w2, zp0[2]);
            }
        }
        l2d += (double)ssum;

        // intra-warp reduce over g (lanes 4,8,16 apart share same c)
        #pragma unroll
        for (int o = 0; o < 3; o++){
            zp0[o] += __shfl_xor_sync(~0u, zp0[o], 4);
            zp0[o] += __shfl_xor_sync(~0u, zp0[o], 8);
            zp0[o] += __shfl_xor_sync(~0u, zp0[o], 16);
            zp1[o] += __shfl_xor_sync(~0u, zp1[o], 4);
            zp1[o] += __shfl_xor_sync(~0u, zp1[o], 8);
            zp1[o] += __shfl_xor_sync(~0u, zp1[o], 16);
        }
        if (l < 4){
            #pragma unroll
            for (int o = 0; o < 3; o++){
                zpS[w * 26 + (2 * c) * 3 + o]     = zp0[o];
                zpS[w * 26 + (2 * c + 1) * 3 + o] = zp1[o];
            }
        }

        __syncthreads();   // barrier 2: rbf[nxt] + zpS published

        // ---- phase 3: finalize z; warp w (<8) -> batch row w ----
        if (w < ROWS){
            #pragma unroll
            for (int o = 0; o < 3; o++){
                float v = (l < 16) ? zpS[l * 26 + w * 3 + o] : 0.f;
                v += __shfl_xor_sync(~0u, v, 1);
                v += __shfl_xor_sync(~0u, v, 2);
                v += __shfl_xor_sync(~0u, v, 4);
                v += __shfl_xor_sync(~0u, v, 8);
                if (l == 0){
                    float bo = (o == 0) ? bo0 : ((o == 1) ? bo1 : bo2);
                    out[((size_t)(b0 + w) * TDIM + ts) * NOUT + o] = v + bo;
                }
            }
        }
    }

    // ---- deterministic l2 reduction, last-block finalization ----
    __syncthreads();
    double* dd = (double*)(sm + UD_OFF);
    dd[tid] = l2d;
    __syncthreads();
    if (tid == 0){
        double s = 0.0;
        for (int i = 0; i < NT; i++) s += dd[i];
        g_l2p[blockIdx.x] = (float)s;
        __threadfence();
        unsigned int old = atomicInc(&g_ctr, NB - 1);
        if (old == NB - 1){
            __threadfence();
            double tot = 0.0;
            for (int i = 0; i < NB; i++) tot += (double)g_l2p[i];
            out[out_size - 1] = (float)(tot / ((double)TDIM * BATCH * NREC));
        }
    }
}

extern "C" void kernel_launch(void* const* d_in, const int* in_sizes, int n_in,
                              void* d_out, int out_size)
{
    const float* x     = (const float*)d_in[0];
    const float* noise = (const float*)d_in[1];
    const float* W_in  = (const float*)d_in[2];
    const float* W_rec = (const float*)d_in[3];
    const float* W_out = (const float*)d_in[4];
    const float* b_out = (const float*)d_in[5];
    const float* bias  = (const float*)d_in[6];
    float* out = (float*)d_out;

    cudaFuncSetAttribute(rnn_kernel, cudaFuncAttributeMaxDynamicSharedMemorySize, SMEM_BYTES);
    prep_kernel<<<32, 256>>>(W_rec);
    rnn_kernel<<<NB, NT, SMEM_BYTES>>>(x, noise, W_in, W_rec, W_out, b_out, bias, out, out_size);
}